// round 16
// baseline (speedup 1.0000x reference)
#include <cuda_runtime.h>
#include <cuda_bf16.h>

// SAConv: B=4, C=G=COUT=64, D=1, H=W=56, K=7, PAD=3, RDIM=256.
//   q = x*wq; logit_t = (q+u)*wk*xw_t + (q+v)*ro_t,  ro_t = sum_c Wr[g,c]*r[g*4+c,t]
//   out = wv * sum_t softmax(logit)_t * xw_t   (no max-subtraction; |logit| small)
// Each block processes TWO planes with the same group g (batches b and b+2):
// the ro broadcast LDS and all per-g setup are shared across both, and the
// grid (896 blocks @ 6/SM = 888 slots) runs as ~one perfect wave.
// u64-native f32x2 datapath as before.

#define KW    7
#define PADX  3
#define HH    56
#define WW    56
#define TH    8           // output rows per block tile -> grid = 7 x 128 = 896
#define PW    62          // padded width 56+6
#define SROWS (TH + 6)    // 14 padded rows staged
#define PLANE (HH * WW)   // 3136
#define NT    224         // 28 col-pairs x 8 rows; 2 adjacent pixels x 2 planes per thread
#define LOG2E 1.4426950408889634f

typedef unsigned long long u64;

__device__ __forceinline__ float ex2a(float x) {
    float y; asm("ex2.approx.ftz.f32 %0, %1;" : "=f"(y) : "f"(x)); return y;
}
__device__ __forceinline__ float rcpa(float x) {
    float y; asm("rcp.approx.ftz.f32 %0, %1;" : "=f"(y) : "f"(x)); return y;
}
__device__ __forceinline__ u64 pack2(float lo, float hi) {
    u64 r; asm("mov.b64 %0, {%1, %2};" : "=l"(r) : "f"(lo), "f"(hi)); return r;
}
__device__ __forceinline__ void unpack2(float& lo, float& hi, u64 v) {
    asm("mov.b64 {%0, %1}, %2;" : "=f"(lo), "=f"(hi) : "l"(v));
}
__device__ __forceinline__ float lo32(u64 v) { float a, b; unpack2(a, b, v); return a; }
__device__ __forceinline__ float hi32(u64 v) { float a, b; unpack2(a, b, v); return b; }
__device__ __forceinline__ u64 combo(u64 a, u64 b) { return pack2(hi32(a), lo32(b)); }
__device__ __forceinline__ u64 mul2(u64 a, u64 b) {
    u64 r; asm("mul.rn.f32x2 %0, %1, %2;" : "=l"(r) : "l"(a), "l"(b)); return r;
}
__device__ __forceinline__ u64 add2(u64 a, u64 b) {
    u64 r; asm("add.rn.f32x2 %0, %1, %2;" : "=l"(r) : "l"(a), "l"(b)); return r;
}
__device__ __forceinline__ u64 fma2(u64 a, u64 b, u64 c) {
    u64 r; asm("fma.rn.f32x2 %0, %1, %2, %3;" : "=l"(r) : "l"(a), "l"(b), "l"(c)); return r;
}
__device__ __forceinline__ u64 exp2_pair(u64 l) {
    float a, b; unpack2(a, b, l);
    return pack2(ex2a(a), ex2a(b));
}

__global__ __launch_bounds__(NT, 6)
void saconv_kernel(const float* __restrict__ x,  const float* __restrict__ r,
                   const float* __restrict__ Wq, const float* __restrict__ Wk,
                   const float* __restrict__ Wv, const float* __restrict__ Wr,
                   const float* __restrict__ up, const float* __restrict__ vp,
                   float* __restrict__ out)
{
    __shared__ float sp[2 * SROWS * PW];   // two staged plane slices
    __shared__ u64  rod[49];               // ro_t duplicated in both 32-bit lanes

    const int tile   = blockIdx.x;         // 0..6 (row tiles)
    const int plane0 = blockIdx.y;         // 0..127 ; partner plane = plane0 + 128
    const int g      = plane0 & 63;
    const int tid    = threadIdx.x;
    const int h0     = tile * TH;

    // Stage padded slices of both planes.
    const float* xp0 = x + (size_t)plane0 * PLANE;
    const float* xp1 = xp0 + 128 * PLANE;
    #pragma unroll
    for (int k = 0; k < (SROWS * PW + NT - 1) / NT; k++) {
        int idx = tid + k * NT;
        if (idx < SROWS * PW) {
            int pr = idx / PW, pc = idx - pr * PW;
            int gh = h0 + pr - PADX;
            int gw = pc - PADX;
            float v0 = 0.0f, v1 = 0.0f;
            if ((unsigned)gh < HH && (unsigned)gw < WW) {
                v0 = xp0[gh * WW + gw];
                v1 = xp1[gh * WW + gw];
            }
            sp[idx] = v0;
            sp[idx + SROWS * PW] = v1;
        }
    }

    // ro[t] = sum_c Wr[g,0,c] * r[g*4+c, t], duplicated into both lanes.
    if (tid < 49) {
        float s = 0.0f;
        #pragma unroll
        for (int c = 0; c < 4; c++)
            s = fmaf(Wr[g * 4 + c], r[(g * 4 + c) * 49 + tid], s);
        rod[tid] = pack2(s, s);
    }
    __syncthreads();

    const float wq = Wq[g], wk = Wk[g], wvw = Wv[g];
    const float u  = up[g], v  = vp[g];

    const int cp = tid % 28;               // column pair: cols 2cp, 2cp+1
    const int rg = tid / 28;               // output row within tile: 0..7
    const float* baseA = sp + rg * PW + 2 * cp;          // plane0 window origin
    const float* baseB = baseA + SROWS * PW;             // plane1 window origin
    float* outp = out + (size_t)plane0 * PLANE + (size_t)(h0 + rg) * WW + 2 * cp;

    // Per-pixel affine coefficients (log2 domain) for both planes.
    float qA0 = baseA[3 * PW + 3] * wq, qA1 = baseA[3 * PW + 4] * wq;
    float qB0 = baseB[3 * PW + 3] * wq, qB1 = baseB[3 * PW + 4] * wq;
    u64 aA = pack2((qA0 + u) * wk * LOG2E, (qA1 + u) * wk * LOG2E);
    u64 bA = pack2((qA0 + v) * LOG2E,      (qA1 + v) * LOG2E);
    u64 aB = pack2((qB0 + u) * wk * LOG2E, (qB1 + u) * wk * LOG2E);
    u64 bB = pack2((qB0 + v) * LOG2E,      (qB1 + v) * LOG2E);

    u64 sA = 0, AA = 0, sB = 0, AB = 0;
    #pragma unroll
    for (int i = 0; i < KW; i++) {
        const u64* rpA = (const u64*)(baseA + i * PW);
        const u64* rpB = (const u64*)(baseB + i * PW);
        u64 a0 = rpA[0], a1 = rpA[1], a2 = rpA[2], a3 = rpA[3];
        u64 e0 = rpB[0], e1 = rpB[1], e2 = rpB[2], e3 = rpB[3];
        const u64* rot = rod + i * KW;

        u64 ro, w, l, p;
        #define TERM2(J, WA, WB)                               \
            ro = rot[J];                                       \
            w  = (WA);                                         \
            l  = fma2(aA, w, mul2(bA, ro));                    \
            p  = exp2_pair(l);                                 \
            sA = add2(sA, p);                                  \
            AA = fma2(p, w, AA);                               \
            w  = (WB);                                         \
            l  = fma2(aB, w, mul2(bB, ro));                    \
            p  = exp2_pair(l);                                 \
            sB = add2(sB, p);                                  \
            AB = fma2(p, w, AB);
        TERM2(0, a0, e0)
        TERM2(1, combo(a0, a1), combo(e0, e1))
        TERM2(2, a1, e1)
        TERM2(3, combo(a1, a2), combo(e1, e2))
        TERM2(4, a2, e2)
        TERM2(5, combo(a2, a3), combo(e2, e3))
        TERM2(6, a3, e3)
        #undef TERM2
    }

    float s0, s1, c0, c1;
    float2 o;
    unpack2(s0, s1, sA); unpack2(c0, c1, AA);
    o.x = c0 * wvw * rcpa(s0);
    o.y = c1 * wvw * rcpa(s1);
    *(float2*)outp = o;                              // plane0 STG.64
    unpack2(s0, s1, sB); unpack2(c0, c1, AB);
    o.x = c0 * wvw * rcpa(s0);
    o.y = c1 * wvw * rcpa(s1);
    *(float2*)(outp + 128 * PLANE) = o;              // plane1 STG.64
}

extern "C" void kernel_launch(void* const* d_in, const int* in_sizes, int n_in,
                              void* d_out, int out_size)
{
    const float* x  = (const float*)d_in[0];
    const float* r  = (const float*)d_in[1];
    const float* Wq = (const float*)d_in[2];
    const float* Wk = (const float*)d_in[3];
    const float* Wv = (const float*)d_in[4];
    const float* Wr = (const float*)d_in[5];
    const float* up = (const float*)d_in[6];
    const float* vp = (const float*)d_in[7];
    float* out = (float*)d_out;

    dim3 grid(HH / TH, 128);   // (7 row-tiles, 128 plane-pairs) = 896 blocks
    saconv_kernel<<<grid, NT>>>(x, r, Wq, Wk, Wv, Wr, up, vp, out);
}